// round 1
// baseline (speedup 1.0000x reference)
#include <cuda_runtime.h>
#include <cstdint>

#define ROWSTRIDE 1024    // H*D
#define KV_PAD 68
#define SC_PAD 324
#define NBLK 64           // S / 64
#define SMEM_FLOATS (64*SC_PAD + 64*KV_PAD + 64)

__device__ __forceinline__ float tf32r(float x){
  float y; asm("cvt.rna.tf32.f32 %0, %1;" : "=f"(y) : "f"(x)); return y;
}

__device__ __forceinline__ void mma8(float* c, uint32_t a0,uint32_t a1,uint32_t a2,uint32_t a3,
                                     uint32_t b0, uint32_t b1){
  asm volatile("mma.sync.aligned.m16n8k8.row.col.f32.tf32.tf32.f32 "
    "{%0,%1,%2,%3},{%4,%5,%6,%7},{%8,%9},{%0,%1,%2,%3};\n"
    : "+f"(c[0]),"+f"(c[1]),"+f"(c[2]),"+f"(c[3])
    : "r"(a0),"r"(a1),"r"(a2),"r"(a3),"r"(b0),"r"(b1));
}

// Stage a 64x64 fp32 tile (row stride ROWSTRIDE) into smem [64][KV_PAD],
// applying scale and round-to-nearest tf32 quantization once per element.
__device__ __forceinline__ void stage_tile(const float* __restrict__ g,
                                           float* __restrict__ s, int t, float scl){
  #pragma unroll
  for(int i=0;i<4;i++){
    int idx = i*256 + t;
    int r = idx >> 4;
    int c = (idx & 15) << 2;
    float4 val = *reinterpret_cast<const float4*>(g + (size_t)r*ROWSTRIDE + c);
    val.x = tf32r(val.x*scl); val.y = tf32r(val.y*scl);
    val.z = tf32r(val.z*scl); val.w = tf32r(val.w*scl);
    *reinterpret_cast<float4*>(s + r*KV_PAD + c) = val;
  }
}

__global__ __launch_bounds__(256, 2)
void bsattn_kernel(const float* __restrict__ q, const float* __restrict__ k,
                   const float* __restrict__ v, float* __restrict__ out){
  extern __shared__ float smem[];
  float* s_sc  = smem;                 // 64 x SC_PAD scores / probabilities
  float* s_kv  = smem + 64*SC_PAD;     // 64 x KV_PAD staging tile (Q, then K_j, then V_j)
  float* s_inv = s_kv + 64*KV_PAD;     // 64 row 1/sum

  const int n = blockIdx.x, h = blockIdx.y, b = blockIdx.z;
  const int t = threadIdx.x, w = t>>5, l = t&31;
  const int lg = l>>2, lt = l&3;       // quad group / lane-in-quad

  const size_t base = ((size_t)b*4096)*ROWSTRIDE + (size_t)h*64;

  // ---- stage Q (pre-scaled by 1/sqrt(D)=0.125) and pull A-fragments into registers ----
  stage_tile(q + base + (size_t)n*64*ROWSTRIDE, s_kv, t, 0.125f);
  __syncthreads();

  const int rq = (w&3)*16;
  const int r0 = rq + lg, r1 = r0 + 8;
  float qa[8][4];
  #pragma unroll
  for(int kt=0;kt<8;kt++){
    qa[kt][0] = s_kv[r0*KV_PAD + kt*8 + lt];
    qa[kt][1] = s_kv[r1*KV_PAD + kt*8 + lt];
    qa[kt][2] = s_kv[r0*KV_PAD + kt*8 + lt + 4];
    qa[kt][3] = s_kv[r1*KV_PAD + kt*8 + lt + 4];
  }
  __syncthreads();

  const int kh = (w>>2)*32;   // this warp's 32-key half within a key block

  // ---- pass 1: S = Q K^T per valid key block ----
  for(int slot=0; slot<5; slot++){
    int j = n - 2 + slot;
    if(j < 0 || j >= NBLK) continue;   // uniform across CTA
    stage_tile(k + base + (size_t)j*64*ROWSTRIDE, s_kv, t, 1.0f);
    __syncthreads();
    float acc[4][4];
    #pragma unroll
    for(int nt=0;nt<4;nt++){ acc[nt][0]=acc[nt][1]=acc[nt][2]=acc[nt][3]=0.f; }
    #pragma unroll
    for(int kt=0;kt<8;kt++){
      uint32_t a0=__float_as_uint(qa[kt][0]);
      uint32_t a1=__float_as_uint(qa[kt][1]);
      uint32_t a2=__float_as_uint(qa[kt][2]);
      uint32_t a3=__float_as_uint(qa[kt][3]);
      #pragma unroll
      for(int nt=0;nt<4;nt++){
        int krow = kh + nt*8 + lg;
        uint32_t b0=__float_as_uint(s_kv[krow*KV_PAD + kt*8 + lt]);
        uint32_t b1=__float_as_uint(s_kv[krow*KV_PAD + kt*8 + lt + 4]);
        mma8(acc[nt], a0,a1,a2,a3, b0,b1);
      }
    }
    int cb = slot*64 + kh;
    #pragma unroll
    for(int nt=0;nt<4;nt++){
      float2 v01 = make_float2(acc[nt][0], acc[nt][1]);
      float2 v23 = make_float2(acc[nt][2], acc[nt][3]);
      *reinterpret_cast<float2*>(&s_sc[r0*SC_PAD + cb + nt*8 + 2*lt]) = v01;
      *reinterpret_cast<float2*>(&s_sc[r1*SC_PAD + cb + nt*8 + 2*lt]) = v23;
    }
    __syncthreads();
  }

  // ---- softmax over the valid key range (invalid blocks never touched => skipped) ----
  {
    int row = t>>2, part = t&3;
    int jlo = (n-2 < 0) ? 0 : n-2;
    int jhi = (n+2 > NBLK-1) ? NBLK-1 : n+2;
    int lo = (jlo - (n-2))*64;
    int hi = (jhi - (n-2))*64 + 64;
    float m = -1e30f;
    for(int c = lo + part; c < hi; c += 4)
      m = fmaxf(m, s_sc[row*SC_PAD + c]);
    m = fmaxf(m, __shfl_xor_sync(0xffffffffu, m, 1));
    m = fmaxf(m, __shfl_xor_sync(0xffffffffu, m, 2));
    float sum = 0.f;
    for(int c = lo + part; c < hi; c += 4){
      float p = __expf(s_sc[row*SC_PAD + c] - m);
      p = tf32r(p);                 // quantize P once here (A operand of PV)
      s_sc[row*SC_PAD + c] = p;
      sum += p;
    }
    sum += __shfl_xor_sync(0xffffffffu, sum, 1);
    sum += __shfl_xor_sync(0xffffffffu, sum, 2);
    if(part==0) s_inv[row] = 1.f/sum;
  }
  __syncthreads();

  // ---- pass 2: O = P V per valid key block ----
  float o[4][4];
  #pragma unroll
  for(int nt=0;nt<4;nt++){ o[nt][0]=o[nt][1]=o[nt][2]=o[nt][3]=0.f; }
  const int dh = (w>>2)*32;   // this warp's 32-col d half
  for(int slot=0;slot<5;slot++){
    int j = n - 2 + slot;
    if(j < 0 || j >= NBLK) continue;
    stage_tile(v + base + (size_t)j*64*ROWSTRIDE, s_kv, t, 1.0f);
    __syncthreads();
    #pragma unroll
    for(int kt=0;kt<8;kt++){
      int col = slot*64 + kt*8;
      uint32_t a0=__float_as_uint(s_sc[r0*SC_PAD + col + lt]);
      uint32_t a1=__float_as_uint(s_sc[r1*SC_PAD + col + lt]);
      uint32_t a2=__float_as_uint(s_sc[r0*SC_PAD + col + lt + 4]);
      uint32_t a3=__float_as_uint(s_sc[r1*SC_PAD + col + lt + 4]);
      #pragma unroll
      for(int nt=0;nt<4;nt++){
        int dc = dh + nt*8 + lg;
        uint32_t b0=__float_as_uint(s_kv[(kt*8 + lt    )*KV_PAD + dc]);
        uint32_t b1=__float_as_uint(s_kv[(kt*8 + lt + 4)*KV_PAD + dc]);
        mma8(o[nt], a0,a1,a2,a3, b0,b1);
      }
    }
    __syncthreads();
  }

  // ---- epilogue: normalize rows and store ----
  float i0 = s_inv[r0], i1 = s_inv[r1];
  float* og = out + base + (size_t)n*64*ROWSTRIDE;
  #pragma unroll
  for(int nt=0;nt<4;nt++){
    int c = dh + nt*8 + 2*lt;
    float2 v0 = make_float2(o[nt][0]*i0, o[nt][1]*i0);
    float2 v1 = make_float2(o[nt][2]*i1, o[nt][3]*i1);
    *reinterpret_cast<float2*>(og + (size_t)r0*ROWSTRIDE + c) = v0;
    *reinterpret_cast<float2*>(og + (size_t)r1*ROWSTRIDE + c) = v1;
  }
}

extern "C" void kernel_launch(void* const* d_in, const int* in_sizes, int n_in,
                              void* d_out, int out_size){
  const float* q = (const float*)d_in[0];
  const float* k = (const float*)d_in[1];
  const float* v = (const float*)d_in[2];
  float* out = (float*)d_out;
  const int smem_bytes = SMEM_FLOATS * (int)sizeof(float);   // 100,608 B
  cudaFuncSetAttribute(bsattn_kernel, cudaFuncAttributeMaxDynamicSharedMemorySize, smem_bytes);
  dim3 grid(NBLK, 16, 2);   // (n, h, b) = 2048 CTAs
  bsattn_kernel<<<grid, 256, smem_bytes>>>(q, k, v, out);
}

// round 2
// speedup vs baseline: 2.4098x; 2.4098x over previous
#include <cuda_runtime.h>
#include <cuda_fp16.h>
#include <cstdint>

#define RS 1024          // row stride in floats (H*D)
#define PITCH 72         // halves per smem row (144B, bank-conflict-free for LDSM)
#define NBLK 64
#define L2E 1.4426950408889634f
#define SMEM_BYTES (5*64*PITCH*2)   // Q + 2x(K,V) fp16 tiles = 46080 B

__device__ __forceinline__ uint32_t h2u(float a, float b){
  __half2 h = __floats2half2_rn(a, b);   // low = a, high = b
  return *reinterpret_cast<uint32_t*>(&h);
}
__device__ __forceinline__ float ex2(float x){
  float y; asm("ex2.approx.f32 %0, %1;" : "=f"(y) : "f"(x)); return y;
}
__device__ __forceinline__ void ldsm4(uint32_t* r, uint32_t addr){
  asm volatile("ldmatrix.sync.aligned.m8n8.x4.shared.b16 {%0,%1,%2,%3}, [%4];"
    : "=r"(r[0]),"=r"(r[1]),"=r"(r[2]),"=r"(r[3]) : "r"(addr));
}
__device__ __forceinline__ void ldsm4t(uint32_t* r, uint32_t addr){
  asm volatile("ldmatrix.sync.aligned.m8n8.x4.trans.shared.b16 {%0,%1,%2,%3}, [%4];"
    : "=r"(r[0]),"=r"(r[1]),"=r"(r[2]),"=r"(r[3]) : "r"(addr));
}
__device__ __forceinline__ void mma16(float* c, const uint32_t* a, uint32_t b0, uint32_t b1){
  asm volatile("mma.sync.aligned.m16n8k16.row.col.f32.f16.f16.f32 "
    "{%0,%1,%2,%3},{%4,%5,%6,%7},{%8,%9},{%0,%1,%2,%3};"
    : "+f"(c[0]),"+f"(c[1]),"+f"(c[2]),"+f"(c[3])
    : "r"(a[0]),"r"(a[1]),"r"(a[2]),"r"(a[3]),"r"(b0),"r"(b1));
}

// Stage one 64x64 fp32 tile (gmem, row stride RS) into fp16 smem [64][PITCH],
// scaling + RN-rounding once per element. 128 threads.
__device__ __forceinline__ void stage(const float* __restrict__ g, __half* __restrict__ s,
                                      int t, float scl){
  #pragma unroll
  for(int i=0;i<8;i++){
    int idx = i*128 + t;
    int r = idx>>4, c = (idx&15)<<2;
    float4 v4 = *reinterpret_cast<const float4*>(g + (size_t)r*RS + c);
    uint2 u;
    u.x = h2u(v4.x*scl, v4.y*scl);
    u.y = h2u(v4.z*scl, v4.w*scl);
    *reinterpret_cast<uint2*>(s + r*PITCH + c) = u;
  }
}

__global__ __launch_bounds__(128, 3)
void bsattn16(const float* __restrict__ q, const float* __restrict__ k,
              const float* __restrict__ v, float* __restrict__ out){
  extern __shared__ __half sm[];
  __half* sQ = sm;
  __half* sK0 = sm + 64*PITCH;
  __half* sV0 = sm + 2*64*PITCH;
  __half* sK1 = sm + 3*64*PITCH;
  __half* sV1 = sm + 4*64*PITCH;

  const int n = blockIdx.x, h = blockIdx.y, b = blockIdx.z;
  const int t = threadIdx.x, w = t>>5, l = t&31;
  const int gp = l>>2, lt = l&3;

  // per-lane ldmatrix address offsets (bytes), see fragment-layout derivation
  const uint32_t kb_lane = ((l>>4)*8 + (l&7))*144 + ((l>>3)&1)*16;           // K B-frags
  const uint32_t vb_lane = (((l>>3)&1)*8 + (l&7))*144 + (l>>4)*16;           // V B-frags (trans)
  const uint32_t qa_lane = vb_lane;                                           // Q A-frags

  const size_t base = ((size_t)b*4096)*RS + (size_t)h*64;
  const int jlo = (n-2 < 0) ? 0 : n-2;
  const int jhi = (n+2 > NBLK-1) ? NBLK-1 : n+2;

  // ---- stage Q (scaled by 1/8) and first K/V block ----
  stage(q + base + (size_t)n*64*RS, sQ, t, 0.125f);
  stage(k + base + (size_t)jlo*64*RS, sK0, t, 1.0f);
  stage(v + base + (size_t)jlo*64*RS, sV0, t, 1.0f);
  __syncthreads();

  const uint32_t uQ  = (uint32_t)__cvta_generic_to_shared(sQ);
  const uint32_t uK0 = (uint32_t)__cvta_generic_to_shared(sK0);
  const uint32_t uV0 = (uint32_t)__cvta_generic_to_shared(sV0);
  const uint32_t uK1 = (uint32_t)__cvta_generic_to_shared(sK1);
  const uint32_t uV1 = (uint32_t)__cvta_generic_to_shared(sV1);

  // ---- Q A-fragments: 4 k16-chunks, 4 regs each ----
  uint32_t qa[4][4];
  #pragma unroll
  for(int kc=0;kc<4;kc++)
    ldsm4(qa[kc], uQ + (uint32_t)w*2304 + kc*32 + qa_lane);

  float o[8][4];
  #pragma unroll
  for(int i=0;i<8;i++){ o[i][0]=o[i][1]=o[i][2]=o[i][3]=0.f; }
  float m0=-1e30f, m1=-1e30f, l0=0.f, l1=0.f;

  for(int j=jlo; j<=jhi; j++){
    int cur = (j - jlo)&1;
    // prefetch next K/V block into the alternate buffer (overlaps compute across CTAs)
    if(j < jhi){
      stage(k + base + (size_t)(j+1)*64*RS, cur ? sK0 : sK1, t, 1.0f);
      stage(v + base + (size_t)(j+1)*64*RS, cur ? sV0 : sV1, t, 1.0f);
    }
    const uint32_t ku = cur ? uK1 : uK0;
    const uint32_t vu = cur ? uV1 : uV0;

    // ---- S = Q K^T (registers) ----
    float st[8][4];
    #pragma unroll
    for(int i=0;i<8;i++){ st[i][0]=st[i][1]=st[i][2]=st[i][3]=0.f; }
    #pragma unroll
    for(int kc=0;kc<4;kc++){
      #pragma unroll
      for(int p=0;p<4;p++){
        uint32_t bf[4];
        ldsm4(bf, ku + p*2304 + kc*32 + kb_lane);
        mma16(st[2*p],   qa[kc], bf[0], bf[1]);
        mma16(st[2*p+1], qa[kc], bf[2], bf[3]);
      }
    }

    // ---- online softmax (rows r0=w*16+gp, r1=r0+8) ----
    float bm0=-1e30f, bm1=-1e30f;
    #pragma unroll
    for(int i=0;i<8;i++){
      bm0 = fmaxf(bm0, fmaxf(st[i][0], st[i][1]));
      bm1 = fmaxf(bm1, fmaxf(st[i][2], st[i][3]));
    }
    bm0 = fmaxf(bm0, __shfl_xor_sync(0xffffffffu, bm0, 1));
    bm0 = fmaxf(bm0, __shfl_xor_sync(0xffffffffu, bm0, 2));
    bm1 = fmaxf(bm1, __shfl_xor_sync(0xffffffffu, bm1, 1));
    bm1 = fmaxf(bm1, __shfl_xor_sync(0xffffffffu, bm1, 2));
    float mn0 = fmaxf(m0, bm0), mn1 = fmaxf(m1, bm1);
    float a0 = ex2((m0 - mn0)*L2E), a1 = ex2((m1 - mn1)*L2E);
    m0 = mn0; m1 = mn1;

    float rs0=0.f, rs1=0.f;
    #pragma unroll
    for(int i=0;i<8;i++){
      float p0 = ex2((st[i][0]-m0)*L2E);
      float p1 = ex2((st[i][1]-m0)*L2E);
      float p2 = ex2((st[i][2]-m1)*L2E);
      float p3 = ex2((st[i][3]-m1)*L2E);
      rs0 += p0 + p1; rs1 += p2 + p3;
      st[i][0]=p0; st[i][1]=p1; st[i][2]=p2; st[i][3]=p3;
    }
    // C-fragment layout == A-fragment layout after fp16 pair packing: no shuffles
    uint32_t pa[4][4];
    #pragma unroll
    for(int c=0;c<4;c++){
      pa[c][0] = h2u(st[2*c][0],   st[2*c][1]);
      pa[c][1] = h2u(st[2*c][2],   st[2*c][3]);
      pa[c][2] = h2u(st[2*c+1][0], st[2*c+1][1]);
      pa[c][3] = h2u(st[2*c+1][2], st[2*c+1][3]);
    }
    rs0 += __shfl_xor_sync(0xffffffffu, rs0, 1);
    rs0 += __shfl_xor_sync(0xffffffffu, rs0, 2);
    rs1 += __shfl_xor_sync(0xffffffffu, rs1, 1);
    rs1 += __shfl_xor_sync(0xffffffffu, rs1, 2);
    l0 = l0*a0 + rs0; l1 = l1*a1 + rs1;

    #pragma unroll
    for(int i=0;i<8;i++){ o[i][0]*=a0; o[i][1]*=a0; o[i][2]*=a1; o[i][3]*=a1; }

    // ---- O += P V ----
    #pragma unroll
    for(int kc=0;kc<4;kc++){
      #pragma unroll
      for(int dp=0;dp<4;dp++){
        uint32_t bf[4];
        ldsm4t(bf, vu + kc*2304 + dp*32 + vb_lane);
        mma16(o[2*dp],   pa[kc], bf[0], bf[1]);
        mma16(o[2*dp+1], pa[kc], bf[2], bf[3]);
      }
    }
    __syncthreads();
  }

  // ---- epilogue: normalize, store fp32 ----
  float i0 = 1.f/l0, i1 = 1.f/l1;
  float* og = out + base + (size_t)n*64*RS + (size_t)(w*16)*RS;
  #pragma unroll
  for(int dt=0; dt<8; dt++){
    int col = dt*8 + 2*lt;
    float2 v0 = make_float2(o[dt][0]*i0, o[dt][1]*i0);
    float2 v1 = make_float2(o[dt][2]*i1, o[dt][3]*i1);
    *reinterpret_cast<float2*>(og + (size_t)gp*RS + col) = v0;
    *reinterpret_cast<float2*>(og + (size_t)(gp+8)*RS + col) = v1;
  }
}

extern "C" void kernel_launch(void* const* d_in, const int* in_sizes, int n_in,
                              void* d_out, int out_size){
  const float* q = (const float*)d_in[0];
  const float* k = (const float*)d_in[1];
  const float* v = (const float*)d_in[2];
  float* out = (float*)d_out;
  cudaFuncSetAttribute(bsattn16, cudaFuncAttributeMaxDynamicSharedMemorySize, SMEM_BYTES);
  dim3 grid(NBLK, 16, 2);
  bsattn16<<<grid, 128, SMEM_BYTES>>>(q, k, v, out);
}